// round 1
// baseline (speedup 1.0000x reference)
#include <cuda_runtime.h>
#include <math.h>

#define BB 2
#define LL 2048
#define DM 1024
#define NH 16
#define DK 64
#define BH (BB*NH)

// ---------------- scratch (static __device__ allocations only) ----------------
__device__ float g_Q[(size_t)BB*NH*LL*DK];     // 16 MB  [b,h,l,d]
__device__ float g_K[(size_t)BB*NH*LL*DK];     // 16 MB
__device__ float g_V[(size_t)BB*NH*LL*DK];     // 16 MB
__device__ float g_C[(size_t)BB*LL*DM];        // 16 MB  context [b,l,(h,d)]
__device__ float g_P[(size_t)BB*NH*LL*LL];     // 537 MB raw logits [bh,q,k]
__device__ float g_m[(size_t)BB*NH*LL];        // row max
__device__ float g_s[(size_t)BB*NH*LL];        // row sumexp
__device__ float g_rb[(size_t)BB*LL];          // log(delta+1e-6)

// ---------------- rel-bias precompute ----------------
__global__ void rb_kernel(const float* __restrict__ delta)
{
    int i = blockIdx.x * 256 + threadIdx.x;
    if (i < BB*LL) g_rb[i] = logf(delta[i] + 1e-6f);
}

// ---------------- QKV projection GEMM ----------------
// A = x [4096,1024] (scaled by delta for V), B = W [1024,1024], out -> [b,h,l,d]
__global__ void qkv_gemm(const float* __restrict__ x, const float* __restrict__ delta,
                         const float* __restrict__ Wq, const float* __restrict__ bq,
                         const float* __restrict__ Wk, const float* __restrict__ bk,
                         const float* __restrict__ Wv, const float* __restrict__ bv)
{
    const int which = blockIdx.z;
    const float* W    = (which == 0) ? Wq : (which == 1) ? Wk : Wv;
    const float* bias = (which == 0) ? bq : (which == 1) ? bk : bv;
    float* O          = (which == 0) ? g_Q : (which == 1) ? g_K : g_V;

    const int m0 = blockIdx.y * 64;
    const int n0 = blockIdx.x * 64;
    __shared__ float As[16][68];   // [k][m]
    __shared__ float Bs[16][68];   // [k][n]

    const int tid = threadIdx.x;
    const int tx = tid & 15, ty = tid >> 4;

    float acc[4][4] = {};

    for (int kk = 0; kk < DM; kk += 16) {
        {   // A tile: 64 rows x 16 cols
            int row = tid >> 2, c4 = (tid & 3) * 4;
            float4 av = *(const float4*)&x[(size_t)(m0 + row) * DM + kk + c4];
            float sc = (which == 2) ? delta[m0 + row] : 1.0f;
            As[c4 + 0][row] = av.x * sc;
            As[c4 + 1][row] = av.y * sc;
            As[c4 + 2][row] = av.z * sc;
            As[c4 + 3][row] = av.w * sc;
        }
        {   // B tile: 16 rows x 64 cols
            int r = tid >> 4, c = (tid & 15) * 4;
            float4 bv4 = *(const float4*)&W[(size_t)(kk + r) * DM + n0 + c];
            Bs[r][c + 0] = bv4.x; Bs[r][c + 1] = bv4.y;
            Bs[r][c + 2] = bv4.z; Bs[r][c + 3] = bv4.w;
        }
        __syncthreads();
        #pragma unroll
        for (int k = 0; k < 16; k++) {
            float a[4], b4[4];
            #pragma unroll
            for (int i = 0; i < 4; i++) a[i]  = As[k][ty * 4 + i];
            #pragma unroll
            for (int j = 0; j < 4; j++) b4[j] = Bs[k][tx * 4 + j];
            #pragma unroll
            for (int i = 0; i < 4; i++)
                #pragma unroll
                for (int j = 0; j < 4; j++)
                    acc[i][j] += a[i] * b4[j];
        }
        __syncthreads();
    }

    #pragma unroll
    for (int i = 0; i < 4; i++) {
        int gm = m0 + ty * 4 + i;
        int b = gm / LL, l = gm % LL;
        #pragma unroll
        for (int j = 0; j < 4; j++) {
            int gn = n0 + tx * 4 + j;
            int h = gn >> 6, d = gn & 63;
            O[(((size_t)(b * NH + h)) * LL + l) * DK + d] = acc[i][j] + bias[gn];
        }
    }
}

// ---------------- scores + online softmax stats ----------------
// block = (qt, bh). Computes 64 q-rows against all 2048 keys; writes raw
// logits to g_P, tracks row max & sumexp via 16-lane butterflies.
__global__ void scores_kernel()
{
    const int bh = blockIdx.y;
    const int b  = bh / NH;
    const int q0 = blockIdx.x * 64;

    __shared__ float Qs[64][65];   // [d][m]
    __shared__ float Ks[64][65];   // [d][n]

    const int tid = threadIdx.x;
    const int tx = tid & 15, ty = tid >> 4;

    {   // load Q tile transposed
        int row = tid >> 2, c0 = (tid & 3) * 16;
        const float* qp = &g_Q[(((size_t)bh) * LL + q0 + row) * DK + c0];
        #pragma unroll
        for (int it = 0; it < 4; it++) {
            float4 v = *(const float4*)(qp + it * 4);
            int d = c0 + it * 4;
            Qs[d + 0][row] = v.x; Qs[d + 1][row] = v.y;
            Qs[d + 2][row] = v.z; Qs[d + 3][row] = v.w;
        }
    }

    float mreg[4], sreg[4];
    #pragma unroll
    for (int i = 0; i < 4; i++) { mreg[i] = -1e30f; sreg[i] = 0.0f; }

    for (int kt = 0; kt < LL / 64; kt++) {
        __syncthreads();
        {   // load K tile transposed
            int row = tid >> 2, c0 = (tid & 3) * 16;
            const float* kp = &g_K[(((size_t)bh) * LL + kt * 64 + row) * DK + c0];
            #pragma unroll
            for (int it = 0; it < 4; it++) {
                float4 v = *(const float4*)(kp + it * 4);
                int d = c0 + it * 4;
                Ks[d + 0][row] = v.x; Ks[d + 1][row] = v.y;
                Ks[d + 2][row] = v.z; Ks[d + 3][row] = v.w;
            }
        }
        __syncthreads();

        float acc[4][4] = {};
        #pragma unroll 16
        for (int d = 0; d < 64; d++) {
            float a[4], b4[4];
            #pragma unroll
            for (int i = 0; i < 4; i++) a[i]  = Qs[d][ty * 4 + i];
            #pragma unroll
            for (int j = 0; j < 4; j++) b4[j] = Ks[d][tx * 4 + j];
            #pragma unroll
            for (int i = 0; i < 4; i++)
                #pragma unroll
                for (int j = 0; j < 4; j++)
                    acc[i][j] += a[i] * b4[j];
        }

        // bias + write logits + online stats
        float rbv[4];
        #pragma unroll
        for (int j = 0; j < 4; j++)
            rbv[j] = g_rb[(size_t)b * LL + kt * 64 + tx * 4 + j];

        #pragma unroll
        for (int i = 0; i < 4; i++) {
            int qg = q0 + ty * 4 + i;
            float sv[4];
            #pragma unroll
            for (int j = 0; j < 4; j++) {
                int kg = kt * 64 + tx * 4 + j;
                sv[j] = acc[i][j] * 0.125f - 0.1f * fabsf((float)(qg - kg)) + rbv[j];
            }
            *(float4*)&g_P[(((size_t)bh) * LL + qg) * LL + kt * 64 + tx * 4] =
                make_float4(sv[0], sv[1], sv[2], sv[3]);

            float tm = fmaxf(fmaxf(sv[0], sv[1]), fmaxf(sv[2], sv[3]));
            #pragma unroll
            for (int o = 8; o >= 1; o >>= 1)
                tm = fmaxf(tm, __shfl_xor_sync(0xffffffffu, tm, o, 16));
            float newm = fmaxf(mreg[i], tm);
            float ls = expf(sv[0] - newm) + expf(sv[1] - newm) +
                       expf(sv[2] - newm) + expf(sv[3] - newm);
            #pragma unroll
            for (int o = 8; o >= 1; o >>= 1)
                ls += __shfl_xor_sync(0xffffffffu, ls, o, 16);
            sreg[i] = sreg[i] * expf(mreg[i] - newm) + ls;
            mreg[i] = newm;
        }
    }

    if (tx == 0) {
        #pragma unroll
        for (int i = 0; i < 4; i++) {
            size_t ridx = (size_t)bh * LL + q0 + ty * 4 + i;
            g_m[ridx] = mreg[i];
            g_s[ridx] = sreg[i];
        }
    }
}

// ---------------- context = softmax(P) @ V ----------------
__global__ void context_kernel()
{
    const int bh = blockIdx.y;
    const int b = bh / NH, h = bh % NH;
    const int q0 = blockIdx.x * 64;

    __shared__ float Ps[64][65];   // [key][m], normalized prob
    __shared__ float Vs[64][65];   // [key][d]
    __shared__ float mrow[64], irow[64];

    const int tid = threadIdx.x;
    const int tx = tid & 15, ty = tid >> 4;

    if (tid < 64) {
        size_t ridx = (size_t)bh * LL + q0 + tid;
        mrow[tid] = g_m[ridx];
        irow[tid] = 1.0f / g_s[ridx];
    }
    __syncthreads();

    float acc[4][4] = {};

    for (int kt = 0; kt < LL / 64; kt++) {
        {   // P tile -> prob, transposed [key][q]
            int row = tid >> 2, c0 = (tid & 3) * 16;
            float mm = mrow[row], ii = irow[row];
            const float* pp = &g_P[(((size_t)bh) * LL + q0 + row) * LL + kt * 64 + c0];
            #pragma unroll
            for (int it = 0; it < 4; it++) {
                float4 v = *(const float4*)(pp + it * 4);
                int k = c0 + it * 4;
                Ps[k + 0][row] = expf(v.x - mm) * ii;
                Ps[k + 1][row] = expf(v.y - mm) * ii;
                Ps[k + 2][row] = expf(v.z - mm) * ii;
                Ps[k + 3][row] = expf(v.w - mm) * ii;
            }
            // V tile [key][d]
            const float* vp = &g_V[(((size_t)bh) * LL + kt * 64 + row) * DK + c0];
            #pragma unroll
            for (int it = 0; it < 4; it++) {
                float4 v = *(const float4*)(vp + it * 4);
                int d = c0 + it * 4;
                Vs[row][d + 0] = v.x; Vs[row][d + 1] = v.y;
                Vs[row][d + 2] = v.z; Vs[row][d + 3] = v.w;
            }
        }
        __syncthreads();
        #pragma unroll 16
        for (int k = 0; k < 64; k++) {
            float a[4], b4[4];
            #pragma unroll
            for (int i = 0; i < 4; i++) a[i]  = Ps[k][ty * 4 + i];
            #pragma unroll
            for (int j = 0; j < 4; j++) b4[j] = Vs[k][tx * 4 + j];
            #pragma unroll
            for (int i = 0; i < 4; i++)
                #pragma unroll
                for (int j = 0; j < 4; j++)
                    acc[i][j] += a[i] * b4[j];
        }
        __syncthreads();
    }

    #pragma unroll
    for (int i = 0; i < 4; i++) {
        int q = q0 + ty * 4 + i;
        *(float4*)&g_C[((size_t)(b * LL + q)) * DM + h * 64 + tx * 4] =
            make_float4(acc[i][0], acc[i][1], acc[i][2], acc[i][3]);
    }
}

// ---------------- head-mean of attention ----------------
__global__ void mean_kernel(float* __restrict__ outmean)
{
    size_t idx = (size_t)blockIdx.x * 256 + threadIdx.x;   // over b*L*L
    int k = (int)(idx % LL);
    size_t bq = idx / LL;
    int q = (int)(bq % LL);
    int b = (int)(bq / LL);
    float acc = 0.0f;
    #pragma unroll
    for (int h = 0; h < NH; h++) {
        int bh = b * NH + h;
        size_t ridx = (size_t)bh * LL + q;
        float p = expf(g_P[((size_t)bh * LL + q) * LL + k] - g_m[ridx]) / g_s[ridx];
        acc += p;
    }
    outmean[idx] = acc * (1.0f / NH);
}

// ---------------- output projection ----------------
__global__ void out_gemm(const float* __restrict__ Wo, const float* __restrict__ bo,
                         float* __restrict__ out)
{
    const int m0 = blockIdx.y * 64;
    const int n0 = blockIdx.x * 64;
    __shared__ float As[16][68];
    __shared__ float Bs[16][68];

    const int tid = threadIdx.x;
    const int tx = tid & 15, ty = tid >> 4;

    float acc[4][4] = {};

    for (int kk = 0; kk < DM; kk += 16) {
        {
            int row = tid >> 2, c4 = (tid & 3) * 4;
            float4 av = *(const float4*)&g_C[(size_t)(m0 + row) * DM + kk + c4];
            As[c4 + 0][row] = av.x; As[c4 + 1][row] = av.y;
            As[c4 + 2][row] = av.z; As[c4 + 3][row] = av.w;
        }
        {
            int r = tid >> 4, c = (tid & 15) * 4;
            float4 bv4 = *(const float4*)&Wo[(size_t)(kk + r) * DM + n0 + c];
            Bs[r][c + 0] = bv4.x; Bs[r][c + 1] = bv4.y;
            Bs[r][c + 2] = bv4.z; Bs[r][c + 3] = bv4.w;
        }
        __syncthreads();
        #pragma unroll
        for (int k = 0; k < 16; k++) {
            float a[4], b4[4];
            #pragma unroll
            for (int i = 0; i < 4; i++) a[i]  = As[k][ty * 4 + i];
            #pragma unroll
            for (int j = 0; j < 4; j++) b4[j] = Bs[k][tx * 4 + j];
            #pragma unroll
            for (int i = 0; i < 4; i++)
                #pragma unroll
                for (int j = 0; j < 4; j++)
                    acc[i][j] += a[i] * b4[j];
        }
        __syncthreads();
    }

    #pragma unroll
    for (int i = 0; i < 4; i++) {
        int gm = m0 + ty * 4 + i;
        #pragma unroll
        for (int j = 0; j < 4; j++) {
            int gn = n0 + tx * 4 + j;
            out[(size_t)gm * DM + gn] = acc[i][j] + bo[gn];
        }
    }
}

// ---------------- launch ----------------
extern "C" void kernel_launch(void* const* d_in, const int* in_sizes, int n_in,
                              void* d_out, int out_size)
{
    const float* x     = (const float*)d_in[0];
    const float* delta = (const float*)d_in[1];
    const float* Wq    = (const float*)d_in[2];
    const float* bq    = (const float*)d_in[3];
    const float* Wk    = (const float*)d_in[4];
    const float* bk    = (const float*)d_in[5];
    const float* Wv    = (const float*)d_in[6];
    const float* bv    = (const float*)d_in[7];
    const float* Wo    = (const float*)d_in[8];
    const float* bo    = (const float*)d_in[9];
    float* out = (float*)d_out;
    float* outmean = out + (size_t)BB * LL * DM;

    rb_kernel<<<(BB * LL + 255) / 256, 256>>>(delta);
    qkv_gemm<<<dim3(DM / 64, (BB * LL) / 64, 3), 256>>>(x, delta, Wq, bq, Wk, bk, Wv, bv);
    scores_kernel<<<dim3(LL / 64, BH), 256>>>();
    context_kernel<<<dim3(LL / 64, BH), 256>>>();
    mean_kernel<<<(unsigned)((size_t)BB * LL * LL / 256), 256>>>(outmean);
    out_gemm<<<dim3(DM / 64, (BB * LL) / 64), 256>>>(Wo, bo, out);
}

// round 2
// speedup vs baseline: 1.3709x; 1.3709x over previous
#include <cuda_runtime.h>
#include <math.h>

#define BB 2
#define LL 2048
#define DM 1024
#define NH 16
#define DK 64
#define BH (BB*NH)

// ---------------- scratch (static __device__ allocations only) ----------------
__device__ float g_Q[(size_t)BB*NH*LL*DK];     // 16 MB  [b,h,l,d]
__device__ float g_K[(size_t)BB*NH*LL*DK];     // 16 MB
__device__ float g_V[(size_t)BB*NH*LL*DK];     // 16 MB
__device__ float g_C[(size_t)BB*LL*DM];        // 16 MB  context [b,l,(h,d)]
__device__ float g_P[(size_t)BB*NH*LL*LL];     // 537 MB raw logits [bh,q,k]
__device__ float g_m[(size_t)BB*NH*LL];        // row max
__device__ float g_s[(size_t)BB*NH*LL];        // row sumexp
__device__ float g_c[(size_t)BB*NH*LL];        // m + log(s)
__device__ float g_rb[(size_t)BB*LL];          // log(delta+1e-6)

// ---------------- rel-bias precompute ----------------
__global__ void rb_kernel(const float* __restrict__ delta)
{
    int i = blockIdx.x * 256 + threadIdx.x;
    if (i < BB*LL) g_rb[i] = logf(delta[i] + 1e-6f);
}

// ---------------- c = m + log(s) precompute ----------------
__global__ void c_kernel()
{
    int i = blockIdx.x * 256 + threadIdx.x;
    if (i < BH*LL) g_c[i] = g_m[i] + __logf(g_s[i]);
}

// ---------------- QKV projection GEMM (128x128 tile, 8x8/thread) ----------------
__global__ void qkv_gemm(const float* __restrict__ x, const float* __restrict__ delta,
                         const float* __restrict__ Wq, const float* __restrict__ bq,
                         const float* __restrict__ Wk, const float* __restrict__ bk,
                         const float* __restrict__ Wv, const float* __restrict__ bv)
{
    const int which = blockIdx.z;
    const float* W    = (which == 0) ? Wq : (which == 1) ? Wk : Wv;
    const float* bias = (which == 0) ? bq : (which == 1) ? bk : bv;
    float* O          = (which == 0) ? g_Q : (which == 1) ? g_K : g_V;

    const int m0 = blockIdx.y * 128;
    const int n0 = blockIdx.x * 128;
    __shared__ float As[16][132];   // [k][m]
    __shared__ float Bs[16][132];   // [k][n]

    const int tid = threadIdx.x;
    const int tx = tid & 15, ty = tid >> 4;

    const int arow = tid >> 1, acol = (tid & 1) * 8;
    const int brow = tid >> 4, bcol = (tid & 15) * 8;
    const float ascale = (which == 2) ? delta[m0 + arow] : 1.0f;

    float acc[8][8] = {};

    for (int kk = 0; kk < DM; kk += 16) {
        if (kk) __syncthreads();
        {   // A tile 128x16 -> transposed
            const float* ap = &x[(size_t)(m0 + arow) * DM + kk + acol];
            float4 a0 = *(const float4*)(ap);
            float4 a1 = *(const float4*)(ap + 4);
            As[acol + 0][arow] = a0.x * ascale; As[acol + 1][arow] = a0.y * ascale;
            As[acol + 2][arow] = a0.z * ascale; As[acol + 3][arow] = a0.w * ascale;
            As[acol + 4][arow] = a1.x * ascale; As[acol + 5][arow] = a1.y * ascale;
            As[acol + 6][arow] = a1.z * ascale; As[acol + 7][arow] = a1.w * ascale;
        }
        {   // B tile 16x128 -> direct
            const float* bp = &W[(size_t)(kk + brow) * DM + n0 + bcol];
            *(float4*)&Bs[brow][bcol]     = *(const float4*)(bp);
            *(float4*)&Bs[brow][bcol + 4] = *(const float4*)(bp + 4);
        }
        __syncthreads();
        #pragma unroll
        for (int k = 0; k < 16; k++) {
            float4 a0 = *(const float4*)&As[k][ty * 4];
            float4 a1 = *(const float4*)&As[k][64 + ty * 4];
            float4 b0 = *(const float4*)&Bs[k][tx * 4];
            float4 b1 = *(const float4*)&Bs[k][64 + tx * 4];
            float a[8] = {a0.x, a0.y, a0.z, a0.w, a1.x, a1.y, a1.z, a1.w};
            float b8[8] = {b0.x, b0.y, b0.z, b0.w, b1.x, b1.y, b1.z, b1.w};
            #pragma unroll
            for (int i = 0; i < 8; i++)
                #pragma unroll
                for (int j = 0; j < 8; j++)
                    acc[i][j] += a[i] * b8[j];
        }
    }

    #pragma unroll
    for (int i = 0; i < 8; i++) {
        int gm = m0 + (i >> 2) * 64 + ty * 4 + (i & 3);
        int b = gm >> 11, l = gm & (LL - 1);
        #pragma unroll
        for (int gj = 0; gj < 2; gj++) {
            int gn = n0 + gj * 64 + tx * 4;
            int h = gn >> 6, d = gn & 63;
            float4 v = make_float4(acc[i][gj*4+0] + bias[gn+0],
                                   acc[i][gj*4+1] + bias[gn+1],
                                   acc[i][gj*4+2] + bias[gn+2],
                                   acc[i][gj*4+3] + bias[gn+3]);
            *(float4*)&O[(((size_t)(b * NH + h)) * LL + l) * DK + d] = v;
        }
    }
}

// ---------------- scores (128q x 128k tile, 8x8/thread) + online stats ----------------
__global__ void scores_kernel()
{
    const int bh = blockIdx.y;
    const int b  = bh >> 4;
    const int q0 = blockIdx.x * 128;

    __shared__ float Qs[32][132];   // [d][q]
    __shared__ float Ks[32][132];   // [d][k]

    const int tid = threadIdx.x;
    const int tx = tid & 15, ty = tid >> 4;
    const int lrow = tid >> 1, lcolh = (tid & 1) * 16;

    const float* Qbase = g_Q + (((size_t)bh) * LL + q0 + lrow) * DK + lcolh;

    float mreg[8], sreg[8];
    #pragma unroll
    for (int i = 0; i < 8; i++) { mreg[i] = -1e30f; sreg[i] = 0.0f; }

    for (int kt = 0; kt < LL / 128; kt++) {
        float acc[8][8] = {};
        const float* Kbase = g_K + (((size_t)bh) * LL + kt * 128 + lrow) * DK + lcolh;

        #pragma unroll
        for (int dc = 0; dc < 64; dc += 32) {
            __syncthreads();
            #pragma unroll
            for (int it = 0; it < 4; it++) {
                float4 qv = *(const float4*)(Qbase + dc + it * 4);
                int d = lcolh + it * 4;
                Qs[d + 0][lrow] = qv.x; Qs[d + 1][lrow] = qv.y;
                Qs[d + 2][lrow] = qv.z; Qs[d + 3][lrow] = qv.w;
                float4 kv = *(const float4*)(Kbase + dc + it * 4);
                Ks[d + 0][lrow] = kv.x; Ks[d + 1][lrow] = kv.y;
                Ks[d + 2][lrow] = kv.z; Ks[d + 3][lrow] = kv.w;
            }
            __syncthreads();
            #pragma unroll
            for (int d = 0; d < 32; d++) {
                float4 a0 = *(const float4*)&Qs[d][ty * 4];
                float4 a1 = *(const float4*)&Qs[d][64 + ty * 4];
                float4 b0 = *(const float4*)&Ks[d][tx * 4];
                float4 b1 = *(const float4*)&Ks[d][64 + tx * 4];
                float a[8] = {a0.x, a0.y, a0.z, a0.w, a1.x, a1.y, a1.z, a1.w};
                float b8[8] = {b0.x, b0.y, b0.z, b0.w, b1.x, b1.y, b1.z, b1.w};
                #pragma unroll
                for (int i = 0; i < 8; i++)
                    #pragma unroll
                    for (int j = 0; j < 8; j++)
                        acc[i][j] += a[i] * b8[j];
            }
        }

        // bias + logits store + online stats
        float rb8[8];
        #pragma unroll
        for (int j = 0; j < 8; j++)
            rb8[j] = g_rb[(size_t)b * LL + kt * 128 + (j >> 2) * 64 + tx * 4 + (j & 3)];

        #pragma unroll
        for (int i = 0; i < 8; i++) {
            int qg = q0 + (i >> 2) * 64 + ty * 4 + (i & 3);
            float sv[8];
            #pragma unroll
            for (int j = 0; j < 8; j++) {
                int kg = kt * 128 + (j >> 2) * 64 + tx * 4 + (j & 3);
                sv[j] = acc[i][j] * 0.125f - 0.1f * fabsf((float)(qg - kg)) + rb8[j];
            }
            float* prow = &g_P[(((size_t)bh) * LL + qg) * LL + kt * 128];
            __stcs((float4*)&prow[tx * 4],      make_float4(sv[0], sv[1], sv[2], sv[3]));
            __stcs((float4*)&prow[64 + tx * 4], make_float4(sv[4], sv[5], sv[6], sv[7]));

            float tm = sv[0];
            #pragma unroll
            for (int j = 1; j < 8; j++) tm = fmaxf(tm, sv[j]);
            #pragma unroll
            for (int o = 8; o >= 1; o >>= 1)
                tm = fmaxf(tm, __shfl_xor_sync(0xffffffffu, tm, o, 16));
            float newm = fmaxf(mreg[i], tm);
            float ls = 0.0f;
            #pragma unroll
            for (int j = 0; j < 8; j++) ls += __expf(sv[j] - newm);
            #pragma unroll
            for (int o = 8; o >= 1; o >>= 1)
                ls += __shfl_xor_sync(0xffffffffu, ls, o, 16);
            sreg[i] = sreg[i] * __expf(mreg[i] - newm) + ls;
            mreg[i] = newm;
        }
    }

    if (tx == 0) {
        #pragma unroll
        for (int i = 0; i < 8; i++) {
            int qg = q0 + (i >> 2) * 64 + ty * 4 + (i & 3);
            size_t ridx = (size_t)bh * LL + qg;
            g_m[ridx] = mreg[i];
            g_s[ridx] = sreg[i];
        }
    }
}

// ---------------- context = softmax(P) @ V  (128q x 64d tile, 8x4/thread) -------
__global__ void context_kernel()
{
    const int bh = blockIdx.y;
    const int b = bh >> 4, h = bh & 15;
    const int q0 = blockIdx.x * 128;

    __shared__ float Ps[32][132];   // [key][q], exp(l - m)
    __shared__ float Vs[32][68];    // [key][d]
    __shared__ float mrow[128], irow[128];

    const int tid = threadIdx.x;
    const int tx = tid & 15, ty = tid >> 4;

    if (tid < 128) {
        size_t ridx = (size_t)bh * LL + q0 + tid;
        mrow[tid] = g_m[ridx];
        irow[tid] = 1.0f / g_s[ridx];
    }

    const int prow = tid >> 1, pk = (tid & 1) * 16;   // P loader
    const int vrow = tid >> 3, vcol = (tid & 7) * 8;  // V loader

    const float* Pbase = g_P + (((size_t)bh) * LL + q0 + prow) * LL + pk;

    float acc[8][4] = {};

    for (int kc = 0; kc < LL; kc += 32) {
        __syncthreads();
        {
            float pm = mrow[prow];
            #pragma unroll
            for (int it = 0; it < 4; it++) {
                float4 v = __ldcs((const float4*)(Pbase + kc + it * 4));
                int k = pk + it * 4;
                Ps[k + 0][prow] = __expf(v.x - pm);
                Ps[k + 1][prow] = __expf(v.y - pm);
                Ps[k + 2][prow] = __expf(v.z - pm);
                Ps[k + 3][prow] = __expf(v.w - pm);
            }
            const float* vp = &g_V[(((size_t)bh) * LL + kc + vrow) * DK + vcol];
            *(float4*)&Vs[vrow][vcol]     = *(const float4*)(vp);
            *(float4*)&Vs[vrow][vcol + 4] = *(const float4*)(vp + 4);
        }
        __syncthreads();
        #pragma unroll
        for (int k = 0; k < 32; k++) {
            float4 a0 = *(const float4*)&Ps[k][ty * 4];
            float4 a1 = *(const float4*)&Ps[k][64 + ty * 4];
            float4 bv4 = *(const float4*)&Vs[k][tx * 4];
            float a[8] = {a0.x, a0.y, a0.z, a0.w, a1.x, a1.y, a1.z, a1.w};
            float b4[4] = {bv4.x, bv4.y, bv4.z, bv4.w};
            #pragma unroll
            for (int i = 0; i < 8; i++)
                #pragma unroll
                for (int j = 0; j < 4; j++)
                    acc[i][j] += a[i] * b4[j];
        }
    }

    #pragma unroll
    for (int i = 0; i < 8; i++) {
        int lq = (i >> 2) * 64 + ty * 4 + (i & 3);
        int q = q0 + lq;
        float sc = irow[lq];
        *(float4*)&g_C[((size_t)(b * LL + q)) * DM + h * 64 + tx * 4] =
            make_float4(acc[i][0] * sc, acc[i][1] * sc, acc[i][2] * sc, acc[i][3] * sc);
    }
}

// ---------------- head-mean of attention (4 k per thread) ----------------
__global__ void mean_kernel(float* __restrict__ outmean)
{
    size_t idx4 = (size_t)blockIdx.x * 256 + threadIdx.x;   // over b*L*L/4
    int k4 = (int)(idx4 & (LL / 4 - 1)) * 4;
    size_t bq = idx4 / (LL / 4);
    int q = (int)(bq & (LL - 1));
    int b = (int)(bq >> 11);
    float ax = 0, ay = 0, az = 0, aw = 0;
    #pragma unroll
    for (int h = 0; h < NH; h++) {
        int bh = b * NH + h;
        float c = g_c[(size_t)bh * LL + q];
        float4 v = __ldcs((const float4*)&g_P[((size_t)bh * LL + q) * LL + k4]);
        ax += __expf(v.x - c); ay += __expf(v.y - c);
        az += __expf(v.z - c); aw += __expf(v.w - c);
    }
    const float inv = 1.0f / NH;
    *(float4*)&outmean[bq * LL + k4] =
        make_float4(ax * inv, ay * inv, az * inv, aw * inv);
}

// ---------------- output projection (128x128 tile, 8x8/thread) ----------------
__global__ void out_gemm(const float* __restrict__ Wo, const float* __restrict__ bo,
                         float* __restrict__ out)
{
    const int m0 = blockIdx.y * 128;
    const int n0 = blockIdx.x * 128;
    __shared__ float As[16][132];
    __shared__ float Bs[16][132];

    const int tid = threadIdx.x;
    const int tx = tid & 15, ty = tid >> 4;
    const int arow = tid >> 1, acol = (tid & 1) * 8;
    const int brow = tid >> 4, bcol = (tid & 15) * 8;

    float acc[8][8] = {};

    for (int kk = 0; kk < DM; kk += 16) {
        if (kk) __syncthreads();
        {
            const float* ap = &g_C[(size_t)(m0 + arow) * DM + kk + acol];
            float4 a0 = *(const float4*)(ap);
            float4 a1 = *(const float4*)(ap + 4);
            As[acol + 0][arow] = a0.x; As[acol + 1][arow] = a0.y;
            As[acol + 2][arow] = a0.z; As[acol + 3][arow] = a0.w;
            As[acol + 4][arow] = a1.x; As[acol + 5][arow] = a1.y;
            As[acol + 6][arow] = a1.z; As[acol + 7][arow] = a1.w;
        }
        {
            const float* bp = &Wo[(size_t)(kk + brow) * DM + n0 + bcol];
            *(float4*)&Bs[brow][bcol]     = *(const float4*)(bp);
            *(float4*)&Bs[brow][bcol + 4] = *(const float4*)(bp + 4);
        }
        __syncthreads();
        #pragma unroll
        for (int k = 0; k < 16; k++) {
            float4 a0 = *(const float4*)&As[k][ty * 4];
            float4 a1 = *(const float4*)&As[k][64 + ty * 4];
            float4 b0 = *(const float4*)&Bs[k][tx * 4];
            float4 b1 = *(const float4*)&Bs[k][64 + tx * 4];
            float a[8] = {a0.x, a0.y, a0.z, a0.w, a1.x, a1.y, a1.z, a1.w};
            float b8[8] = {b0.x, b0.y, b0.z, b0.w, b1.x, b1.y, b1.z, b1.w};
            #pragma unroll
            for (int i = 0; i < 8; i++)
                #pragma unroll
                for (int j = 0; j < 8; j++)
                    acc[i][j] += a[i] * b8[j];
        }
    }

    #pragma unroll
    for (int i = 0; i < 8; i++) {
        int gm = m0 + (i >> 2) * 64 + ty * 4 + (i & 3);
        #pragma unroll
        for (int gj = 0; gj < 2; gj++) {
            int gn = n0 + gj * 64 + tx * 4;
            float4 v = make_float4(acc[i][gj*4+0] + bo[gn+0],
                                   acc[i][gj*4+1] + bo[gn+1],
                                   acc[i][gj*4+2] + bo[gn+2],
                                   acc[i][gj*4+3] + bo[gn+3]);
            *(float4*)&out[(size_t)gm * DM + gn] = v;
        }
    }
}

// ---------------- launch ----------------
extern "C" void kernel_launch(void* const* d_in, const int* in_sizes, int n_in,
                              void* d_out, int out_size)
{
    const float* x     = (const float*)d_in[0];
    const float* delta = (const float*)d_in[1];
    const float* Wq    = (const float*)d_in[2];
    const float* bq    = (const float*)d_in[3];
    const float* Wk    = (const float*)d_in[4];
    const float* bk    = (const float*)d_in[5];
    const float* Wv    = (const float*)d_in[6];
    const float* bv    = (const float*)d_in[7];
    const float* Wo    = (const float*)d_in[8];
    const float* bo    = (const float*)d_in[9];
    float* out = (float*)d_out;
    float* outmean = out + (size_t)BB * LL * DM;

    rb_kernel<<<(BB * LL + 255) / 256, 256>>>(delta);
    qkv_gemm<<<dim3(DM / 128, (BB * LL) / 128, 3), 256>>>(x, delta, Wq, bq, Wk, bk, Wv, bv);
    scores_kernel<<<dim3(LL / 128, BH), 256>>>();
    c_kernel<<<(BH * LL + 255) / 256, 256>>>();
    context_kernel<<<dim3(LL / 128, BH), 256>>>();
    mean_kernel<<<(unsigned)((size_t)BB * LL * LL / 4 / 256), 256>>>(outmean);
    out_gemm<<<dim3(DM / 128, (BB * LL) / 128), 256>>>(Wo, bo, out);
}